// round 4
// baseline (speedup 1.0000x reference)
#include <cuda_runtime.h>

// ---------------------------------------------------------------------------
// Hetero-RGCN, 2 layers, output = chemical nodes.
//   Layer L: for each etype (src->dst):  Wh = h_src @ W + b  (GEMM, fp32)
//            agg[dst] += sum_e Wh[src_e] * inv_deg[dst_e]    (atomic scatter)
//   mean+bias identity: mean(hW+b) = mean(hW)+b (deg>0), 0 (isolated) —
//   so bias lives in the GEMM and isolated nodes stay at the zero init.
//   Layer 2 computes only etypes with dst==chemical (ge2ch, ch2ch).
// ---------------------------------------------------------------------------

#define NNODE 50000
#define DIM   256
#define NE    400000

__device__ __align__(16) float g_Wh[NNODE * DIM];      // per-etype GEMM scratch
__device__ __align__(16) float g_agg_ch[NNODE * DIM];  // layer-1 agg / hidden (chemical)
__device__ __align__(16) float g_agg_ge[NNODE * DIM];  // layer-1 agg / hidden (gene)
__device__ __align__(16) int   g_cnt[4 * NNODE];       // per-etype dst degree
__device__ __align__(16) float g_inv[4 * NNODE];       // 1/max(deg,1)

// ---------------------------------------------------------------- utilities
__global__ void zero_f4(float4* __restrict__ p, int n4) {
    int i = blockIdx.x * blockDim.x + threadIdx.x;
    if (i < n4) p[i] = make_float4(0.f, 0.f, 0.f, 0.f);
}

__global__ void leaky_relu_f4(float4* __restrict__ p, int n4) {
    int i = blockIdx.x * blockDim.x + threadIdx.x;
    if (i < n4) {
        float4 v = p[i];
        v.x = v.x > 0.f ? v.x : 0.01f * v.x;
        v.y = v.y > 0.f ? v.y : 0.01f * v.y;
        v.z = v.z > 0.f ? v.z : 0.01f * v.z;
        v.w = v.w > 0.f ? v.w : 0.01f * v.w;
        p[i] = v;
    }
}

__global__ void count_deg(const int* __restrict__ dst, int E, int* __restrict__ cnt) {
    int i = blockIdx.x * blockDim.x + threadIdx.x;
    if (i < E) atomicAdd(&cnt[dst[i]], 1);
}

__global__ void make_inv(const int* __restrict__ cnt, float* __restrict__ inv, int n) {
    int i = blockIdx.x * blockDim.x + threadIdx.x;
    if (i < n) {
        int c = cnt[i];
        inv[i] = 1.0f / (float)(c > 1 ? c : 1);
    }
}

// ------------------------------------------------------------- fp32 GEMM
// C[M x 256] = A[M x 256] @ W[256 x 256] + bias, row-major, K=N=256 fixed.
// Classic 128x128x8 tile, 8x8 per thread, 256 threads.
#define BM 128
#define BN 128
#define BK 8
#define TM 8
#define TN 8

__global__ __launch_bounds__(256)
void sgemm_bias_256(const float* __restrict__ A,
                    const float* __restrict__ W,
                    const float* __restrict__ bias,
                    float* __restrict__ C, int M)
{
    const int K = 256, N = 256;
    __shared__ float As[BK][BM];  // transposed A tile
    __shared__ float Bs[BK][BN];

    const int tid  = threadIdx.x;
    const int row0 = blockIdx.y * BM;
    const int col0 = blockIdx.x * BN;

    // loaders: A tile 128x8 (one float4/thread), B tile 8x128 (one float4/thread)
    const int aRow = tid >> 1;
    const int aCol = (tid & 1) << 2;
    const int bRow = tid >> 5;
    const int bCol = (tid & 31) << 2;
    // compute mapping: 16x16 thread grid of 8x8 micro-tiles
    const int tRow = (tid >> 4) << 3;
    const int tCol = (tid & 15) << 3;

    float acc[TM][TN];
#pragma unroll
    for (int i = 0; i < TM; i++)
#pragma unroll
        for (int j = 0; j < TN; j++) acc[i][j] = 0.0f;

    const int garow = row0 + aRow;

    for (int k0 = 0; k0 < K; k0 += BK) {
        float4 av = make_float4(0.f, 0.f, 0.f, 0.f);
        if (garow < M)
            av = *reinterpret_cast<const float4*>(A + (size_t)garow * K + k0 + aCol);
        As[aCol + 0][aRow] = av.x;
        As[aCol + 1][aRow] = av.y;
        As[aCol + 2][aRow] = av.z;
        As[aCol + 3][aRow] = av.w;

        float4 bv = *reinterpret_cast<const float4*>(
            W + (size_t)(k0 + bRow) * N + col0 + bCol);
        *reinterpret_cast<float4*>(&Bs[bRow][bCol]) = bv;

        __syncthreads();
#pragma unroll
        for (int k = 0; k < BK; k++) {
            float rM[TM], rN[TN];
#pragma unroll
            for (int i = 0; i < TM; i++) rM[i] = As[k][tRow + i];
#pragma unroll
            for (int j = 0; j < TN; j++) rN[j] = Bs[k][tCol + j];
#pragma unroll
            for (int i = 0; i < TM; i++)
#pragma unroll
                for (int j = 0; j < TN; j++)
                    acc[i][j] = fmaf(rM[i], rN[j], acc[i][j]);
        }
        __syncthreads();
    }

#pragma unroll
    for (int i = 0; i < TM; i++) {
        int gr = row0 + tRow + i;
        if (gr < M) {
#pragma unroll
            for (int j = 0; j < TN; j += 4) {
                int gc = col0 + tCol + j;
                float4 o;
                o.x = acc[i][j + 0] + bias[gc + 0];
                o.y = acc[i][j + 1] + bias[gc + 1];
                o.z = acc[i][j + 2] + bias[gc + 2];
                o.w = acc[i][j + 3] + bias[gc + 3];
                *reinterpret_cast<float4*>(C + (size_t)gr * N + gc) = o;
            }
        }
    }
}

// -------------------------------------------------------- edge aggregation
// One float4 column-chunk per thread: 64 threads cover one edge's 256 floats.
// Gather Wh[src] (L2-resident), scale by inv_deg[dst], vector-RED into agg[dst].
__global__ void edge_agg(const int* __restrict__ src, const int* __restrict__ dst,
                         const float* __restrict__ inv, const float* __restrict__ Wh,
                         float* __restrict__ agg, int E)
{
    int idx = blockIdx.x * blockDim.x + threadIdx.x;
    int e = idx >> 6;
    if (e >= E) return;
    int q = (idx & 63) << 2;
    int s = __ldg(src + e);
    int d = __ldg(dst + e);
    float w = __ldg(inv + d);
    float4 v = *reinterpret_cast<const float4*>(Wh + (size_t)s * DIM + q);
    float* out = agg + (size_t)d * DIM + q;
    asm volatile("red.global.add.v4.f32 [%0], {%1, %2, %3, %4};"
                 :: "l"(out), "f"(v.x * w), "f"(v.y * w), "f"(v.z * w), "f"(v.w * w)
                 : "memory");
}

// --------------------------------------------------------------------- host
extern "C" void kernel_launch(void* const* d_in, const int* in_sizes, int n_in,
                              void* d_out, int out_size)
{
    (void)n_in; (void)out_size;

    const float* emb[2] = {(const float*)d_in[0], (const float*)d_in[1]};
    const float *W1[4], *b1[4], *W2[4], *b2[4];
    const int *src[4], *dst[4];

    // Disambiguate metadata ordering:
    //   dict order (etype-grouped): idx6 is src_ch2ge (400000 elems)
    //   signature order (weights then edges): idx6 is W1_ch2ch (65536 elems)
    bool dict_order = (in_sizes[6] == NE);
    if (dict_order) {
        for (int t = 0; t < 4; t++) {
            const int base = 2 + 6 * t;
            W1[t]  = (const float*)d_in[base + 0];
            b1[t]  = (const float*)d_in[base + 1];
            W2[t]  = (const float*)d_in[base + 2];
            b2[t]  = (const float*)d_in[base + 3];
            src[t] = (const int*)  d_in[base + 4];
            dst[t] = (const int*)  d_in[base + 5];
        }
    } else {
        for (int t = 0; t < 4; t++) {
            W1[t]  = (const float*)d_in[2  + 2 * t];
            b1[t]  = (const float*)d_in[3  + 2 * t];
            W2[t]  = (const float*)d_in[10 + 2 * t];
            b2[t]  = (const float*)d_in[11 + 2 * t];
            src[t] = (const int*)  d_in[18 + 2 * t];
            dst[t] = (const int*)  d_in[19 + 2 * t];
        }
    }

    float *wh, *agg_ch, *agg_ge, *inv;
    int *cnt;
    cudaGetSymbolAddress((void**)&wh,     g_Wh);
    cudaGetSymbolAddress((void**)&agg_ch, g_agg_ch);
    cudaGetSymbolAddress((void**)&agg_ge, g_agg_ge);
    cudaGetSymbolAddress((void**)&cnt,    g_cnt);
    cudaGetSymbolAddress((void**)&inv,    g_inv);

    float* aggs[2] = {agg_ch, agg_ge};
    // etype order: 0=ch2ge, 1=ge2ch, 2=ch2ch, 3=ge2ge
    const int src_nt[4] = {0, 1, 0, 1};   // 0=chemical, 1=gene
    const int dst_nt[4] = {1, 0, 0, 1};

    const int n4 = NNODE * DIM / 4;                 // float4 count per node matrix
    const int edge_blocks = (NE * 64 + 255) / 256;  // 64 threads per edge
    dim3 ggrid(DIM / BN, (NNODE + BM - 1) / BM);

    // degrees -> inv (same graph both layers; recomputed every call: deterministic)
    zero_f4<<<(4 * NNODE / 4 + 255) / 256, 256>>>((float4*)cnt, 4 * NNODE / 4);
    for (int t = 0; t < 4; t++)
        count_deg<<<(NE + 255) / 256, 256>>>(dst[t], NE, cnt + t * NNODE);
    make_inv<<<(4 * NNODE + 255) / 256, 256>>>(cnt, inv, 4 * NNODE);

    // -------- layer 1 (all 4 etypes) --------
    zero_f4<<<(n4 + 255) / 256, 256>>>((float4*)agg_ch, n4);
    zero_f4<<<(n4 + 255) / 256, 256>>>((float4*)agg_ge, n4);
    for (int t = 0; t < 4; t++) {
        sgemm_bias_256<<<ggrid, 256>>>(emb[src_nt[t]], W1[t], b1[t], wh, NNODE);
        edge_agg<<<edge_blocks, 256>>>(src[t], dst[t], inv + t * NNODE,
                                       wh, aggs[dst_nt[t]], NE);
    }
    leaky_relu_f4<<<(n4 + 255) / 256, 256>>>((float4*)agg_ch, n4);
    leaky_relu_f4<<<(n4 + 255) / 256, 256>>>((float4*)agg_ge, n4);

    // -------- layer 2: only dst==chemical etypes matter for the output --------
    zero_f4<<<(n4 + 255) / 256, 256>>>((float4*)d_out, n4);
    // etype 1: ge2ch (src = gene hidden)
    sgemm_bias_256<<<ggrid, 256>>>(agg_ge, W2[1], b2[1], wh, NNODE);
    edge_agg<<<edge_blocks, 256>>>(src[1], dst[1], inv + 1 * NNODE,
                                   wh, (float*)d_out, NE);
    // etype 2: ch2ch (src = chemical hidden)
    sgemm_bias_256<<<ggrid, 256>>>(agg_ch, W2[2], b2[2], wh, NNODE);
    edge_agg<<<edge_blocks, 256>>>(src[2], dst[2], inv + 2 * NNODE,
                                   wh, (float*)d_out, NE);
}

// round 6
// speedup vs baseline: 1.4959x; 1.4959x over previous
#include <cuda_runtime.h>
#include <cuda_bf16.h>
#include <cstdint>

// ---------------------------------------------------------------------------
// Hetero-RGCN, 2 layers, output = chemical nodes.
// GEMMs: mma.sync bf16 (HMMA, sm_80+ ISA — the harness targets compute_100,
// so tcgen05 is unavailable) with 3-term bf16 split for fp32-level accuracy:
//   A*W ~= Ahi*Whi + Alo*Whi + Ahi*Wlo   (lo*lo dropped, ~2^-16 rel)
// Aggregation: per-edge gather + vector RED with 1/deg scaling (verified R3/R4).
// ---------------------------------------------------------------------------

#define NNODE 50000
#define DIM   256
#define NE    400000

__device__ __align__(16) float g_Wh[NNODE * DIM];      // per-etype GEMM scratch
__device__ __align__(16) float g_agg_ch[NNODE * DIM];  // layer-1 agg (chemical)
__device__ __align__(16) float g_agg_ge[NNODE * DIM];  // layer-1 agg (gene)
__device__ __align__(16) int   g_cnt[4 * NNODE];
__device__ __align__(16) float g_inv[4 * NNODE];
// 6 weight matrices transposed to [N][K], bf16 hi+lo: 6 * 2 * 65536
__device__ __align__(16) __nv_bfloat16 g_Wt[6 * 2 * 65536];

// ============================ small utility kernels =========================
__global__ void zero_f4(float4* __restrict__ p, int n4) {
    int i = blockIdx.x * blockDim.x + threadIdx.x;
    if (i < n4) p[i] = make_float4(0.f, 0.f, 0.f, 0.f);
}

__global__ void leaky_relu_f4(float4* __restrict__ p, int n4) {
    int i = blockIdx.x * blockDim.x + threadIdx.x;
    if (i < n4) {
        float4 v = p[i];
        v.x = v.x > 0.f ? v.x : 0.01f * v.x;
        v.y = v.y > 0.f ? v.y : 0.01f * v.y;
        v.z = v.z > 0.f ? v.z : 0.01f * v.z;
        v.w = v.w > 0.f ? v.w : 0.01f * v.w;
        p[i] = v;
    }
}

__global__ void count_deg(const int* __restrict__ dst, int E, int* __restrict__ cnt) {
    int i = blockIdx.x * blockDim.x + threadIdx.x;
    if (i < E) atomicAdd(&cnt[dst[i]], 1);
}

__global__ void make_inv(const int* __restrict__ cnt, float* __restrict__ inv, int n) {
    int i = blockIdx.x * blockDim.x + threadIdx.x;
    if (i < n) {
        int c = cnt[i];
        inv[i] = 1.0f / (float)(c > 1 ? c : 1);
    }
}

// Transpose + bf16 hi/lo split of one 256x256 weight: out[n][k] = W[k][n]
__global__ void split_w(const float* __restrict__ W,
                        __nv_bfloat16* __restrict__ hi,
                        __nv_bfloat16* __restrict__ lo) {
    int i = blockIdx.x * 256 + threadIdx.x;   // 65536 total
    int n = i >> 8, k = i & 255;
    float w = W[k * 256 + n];
    __nv_bfloat16 h = __float2bfloat16_rn(w);
    hi[i] = h;
    lo[i] = __float2bfloat16_rn(w - __bfloat162float(h));
}

// ====================== mma.sync bf16 split GEMM ============================
// C[M x 256] = A[M x 256] @ W + bias. Bhi/Blo: transposed [256 n][256 k] bf16.
// CTA: 128(M) x 128(N), BK=32. 256 threads = 8 warps (2 row x 4 col),
// warp tile 64x32 = 4 m-tiles (m16) x 4 n-tiles (n8), K-step 16.
#define BK 32
#define AST 40   // smem row stride in bf16 (32 + 8 pad) -> conflict-free frags

__device__ __forceinline__ void mma_bf16(float* c, const uint32_t* a,
                                         const uint32_t* b) {
    asm volatile(
        "mma.sync.aligned.m16n8k16.row.col.f32.bf16.bf16.f32 "
        "{%0,%1,%2,%3}, {%4,%5,%6,%7}, {%8,%9}, {%0,%1,%2,%3};"
        : "+f"(c[0]), "+f"(c[1]), "+f"(c[2]), "+f"(c[3])
        : "r"(a[0]), "r"(a[1]), "r"(a[2]), "r"(a[3]), "r"(b[0]), "r"(b[1]));
}

__global__ __launch_bounds__(256, 2)
void gemm_mma(const float* __restrict__ A,
              const __nv_bfloat16* __restrict__ Bhi,
              const __nv_bfloat16* __restrict__ Blo,
              const float* __restrict__ bias,
              float* __restrict__ C, int M)
{
    __shared__ __nv_bfloat16 sAhi[128 * AST];
    __shared__ __nv_bfloat16 sAlo[128 * AST];
    __shared__ __nv_bfloat16 sBhi[128 * AST];
    __shared__ __nv_bfloat16 sBlo[128 * AST];

    const int tid = threadIdx.x;
    const int wid = tid >> 5;
    const int lid = tid & 31;
    const int wr = wid & 1;          // warp row (0,1): 64 rows each
    const int wc = wid >> 1;         // warp col (0..3): 32 cols each
    const int g = lid >> 2;          // group 0..7
    const int t = lid & 3;           // thread-in-group

    const int row0 = blockIdx.y * 128;
    const int col0 = blockIdx.x * 128;

    float acc[4][4][4];
#pragma unroll
    for (int i = 0; i < 4; i++)
#pragma unroll
        for (int j = 0; j < 4; j++)
#pragma unroll
            for (int k = 0; k < 4; k++) acc[i][j][k] = 0.f;

    for (int k0 = 0; k0 < 256; k0 += BK) {
        // ---- load A tile (fp32 -> bf16 hi/lo) : 128 rows x 32 k ----
#pragma unroll
        for (int it = 0; it < 4; ++it) {
            int i  = it * 256 + tid;
            int r  = i >> 3;
            int c4 = i & 7;
            int gr = row0 + r;
            float4 v = make_float4(0.f, 0.f, 0.f, 0.f);
            if (gr < M)
                v = *reinterpret_cast<const float4*>(A + (size_t)gr * 256 + k0 + c4 * 4);
            __nv_bfloat162 h01, h23, l01, l23;
            h01.x = __float2bfloat16_rn(v.x);
            h01.y = __float2bfloat16_rn(v.y);
            h23.x = __float2bfloat16_rn(v.z);
            h23.y = __float2bfloat16_rn(v.w);
            l01.x = __float2bfloat16_rn(v.x - __bfloat162float(h01.x));
            l01.y = __float2bfloat16_rn(v.y - __bfloat162float(h01.y));
            l23.x = __float2bfloat16_rn(v.z - __bfloat162float(h23.x));
            l23.y = __float2bfloat16_rn(v.w - __bfloat162float(h23.y));
            uint2 hv, lv;
            hv.x = *reinterpret_cast<uint32_t*>(&h01);
            hv.y = *reinterpret_cast<uint32_t*>(&h23);
            lv.x = *reinterpret_cast<uint32_t*>(&l01);
            lv.y = *reinterpret_cast<uint32_t*>(&l23);
            *reinterpret_cast<uint2*>(&sAhi[r * AST + c4 * 4]) = hv;
            *reinterpret_cast<uint2*>(&sAlo[r * AST + c4 * 4]) = lv;
        }
        // ---- load B tiles (bf16, K-major [n][k]) : 128 n x 32 k, hi & lo ----
#pragma unroll
        for (int it = 0; it < 2; ++it) {
            int i  = it * 256 + tid;
            int n  = i >> 2;
            int kg = i & 3;
            size_t goff = (size_t)(col0 + n) * 256 + k0 + kg * 8;
            *reinterpret_cast<uint4*>(&sBhi[n * AST + kg * 8]) =
                *reinterpret_cast<const uint4*>(Bhi + goff);
            *reinterpret_cast<uint4*>(&sBlo[n * AST + kg * 8]) =
                *reinterpret_cast<const uint4*>(Blo + goff);
        }
        __syncthreads();

        // ---- compute: 2 k-steps x 3 terms x (4 m x 4 n) mma ----
#pragma unroll
        for (int ks = 0; ks < 2; ++ks) {
            const int kk = ks * 16;
            uint32_t af[4][4], bf[4][2];

            // A-hi fragments
#pragma unroll
            for (int mt = 0; mt < 4; ++mt) {
                const __nv_bfloat16* p = &sAhi[(wr * 64 + mt * 16 + g) * AST + kk + t * 2];
                af[mt][0] = *reinterpret_cast<const uint32_t*>(p);
                af[mt][1] = *reinterpret_cast<const uint32_t*>(p + 8 * AST);
                af[mt][2] = *reinterpret_cast<const uint32_t*>(p + 8);
                af[mt][3] = *reinterpret_cast<const uint32_t*>(p + 8 * AST + 8);
            }
            // B-hi fragments ; term0 = Ahi*Bhi
#pragma unroll
            for (int nt = 0; nt < 4; ++nt) {
                const __nv_bfloat16* p = &sBhi[(wc * 32 + nt * 8 + g) * AST + kk + t * 2];
                bf[nt][0] = *reinterpret_cast<const uint32_t*>(p);
                bf[nt][1] = *reinterpret_cast<const uint32_t*>(p + 8);
            }
#pragma unroll
            for (int mt = 0; mt < 4; ++mt)
#pragma unroll
                for (int nt = 0; nt < 4; ++nt)
                    mma_bf16(acc[mt][nt], af[mt], bf[nt]);

            // B-lo fragments ; term2 = Ahi*Blo
#pragma unroll
            for (int nt = 0; nt < 4; ++nt) {
                const __nv_bfloat16* p = &sBlo[(wc * 32 + nt * 8 + g) * AST + kk + t * 2];
                bf[nt][0] = *reinterpret_cast<const uint32_t*>(p);
                bf[nt][1] = *reinterpret_cast<const uint32_t*>(p + 8);
            }
#pragma unroll
            for (int mt = 0; mt < 4; ++mt)
#pragma unroll
                for (int nt = 0; nt < 4; ++nt)
                    mma_bf16(acc[mt][nt], af[mt], bf[nt]);

            // A-lo fragments, reload B-hi ; term1 = Alo*Bhi
#pragma unroll
            for (int mt = 0; mt < 4; ++mt) {
                const __nv_bfloat16* p = &sAlo[(wr * 64 + mt * 16 + g) * AST + kk + t * 2];
                af[mt][0] = *reinterpret_cast<const uint32_t*>(p);
                af[mt][1] = *reinterpret_cast<const uint32_t*>(p + 8 * AST);
                af[mt][2] = *reinterpret_cast<const uint32_t*>(p + 8);
                af[mt][3] = *reinterpret_cast<const uint32_t*>(p + 8 * AST + 8);
            }
#pragma unroll
            for (int nt = 0; nt < 4; ++nt) {
                const __nv_bfloat16* p = &sBhi[(wc * 32 + nt * 8 + g) * AST + kk + t * 2];
                bf[nt][0] = *reinterpret_cast<const uint32_t*>(p);
                bf[nt][1] = *reinterpret_cast<const uint32_t*>(p + 8);
            }
#pragma unroll
            for (int mt = 0; mt < 4; ++mt)
#pragma unroll
                for (int nt = 0; nt < 4; ++nt)
                    mma_bf16(acc[mt][nt], af[mt], bf[nt]);
        }
        __syncthreads();
    }

    // ---- epilogue: acc + bias -> C ----
#pragma unroll
    for (int nt = 0; nt < 4; ++nt) {
        const int gc = col0 + wc * 32 + nt * 8 + t * 2;
        float2 bb = *reinterpret_cast<const float2*>(bias + gc);
#pragma unroll
        for (int mt = 0; mt < 4; ++mt) {
            int r0 = row0 + wr * 64 + mt * 16 + g;
            if (r0 < M) {
                float2 o;
                o.x = acc[mt][nt][0] + bb.x;
                o.y = acc[mt][nt][1] + bb.y;
                *reinterpret_cast<float2*>(C + (size_t)r0 * 256 + gc) = o;
            }
            if (r0 + 8 < M) {
                float2 o;
                o.x = acc[mt][nt][2] + bb.x;
                o.y = acc[mt][nt][3] + bb.y;
                *reinterpret_cast<float2*>(C + (size_t)(r0 + 8) * 256 + gc) = o;
            }
        }
    }
}

// -------------------------------------------------------- edge aggregation
__global__ void edge_agg(const int* __restrict__ src, const int* __restrict__ dst,
                         const float* __restrict__ inv, const float* __restrict__ Wh,
                         float* __restrict__ agg, int E)
{
    int idx = blockIdx.x * blockDim.x + threadIdx.x;
    int e = idx >> 6;
    if (e >= E) return;
    int q = (idx & 63) << 2;
    int s = __ldg(src + e);
    int d = __ldg(dst + e);
    float w = __ldg(inv + d);
    float4 v = *reinterpret_cast<const float4*>(Wh + (size_t)s * DIM + q);
    float* out = agg + (size_t)d * DIM + q;
    asm volatile("red.global.add.v4.f32 [%0], {%1, %2, %3, %4};"
                 :: "l"(out), "f"(v.x * w), "f"(v.y * w), "f"(v.z * w), "f"(v.w * w)
                 : "memory");
}

// --------------------------------------------------------------------- host
extern "C" void kernel_launch(void* const* d_in, const int* in_sizes, int n_in,
                              void* d_out, int out_size)
{
    (void)n_in; (void)out_size;

    const float* emb[2] = {(const float*)d_in[0], (const float*)d_in[1]};
    const float *W1[4], *b1[4], *W2[4], *b2[4];
    const int *src[4], *dst[4];

    bool dict_order = (in_sizes[6] == NE);
    if (dict_order) {
        for (int t = 0; t < 4; t++) {
            const int base = 2 + 6 * t;
            W1[t]  = (const float*)d_in[base + 0];
            b1[t]  = (const float*)d_in[base + 1];
            W2[t]  = (const float*)d_in[base + 2];
            b2[t]  = (const float*)d_in[base + 3];
            src[t] = (const int*)  d_in[base + 4];
            dst[t] = (const int*)  d_in[base + 5];
        }
    } else {
        for (int t = 0; t < 4; t++) {
            W1[t]  = (const float*)d_in[2  + 2 * t];
            b1[t]  = (const float*)d_in[3  + 2 * t];
            W2[t]  = (const float*)d_in[10 + 2 * t];
            b2[t]  = (const float*)d_in[11 + 2 * t];
            src[t] = (const int*)  d_in[18 + 2 * t];
            dst[t] = (const int*)  d_in[19 + 2 * t];
        }
    }

    float *wh, *agg_ch, *agg_ge, *inv;
    int *cnt;
    __nv_bfloat16* wt;
    cudaGetSymbolAddress((void**)&wh,     g_Wh);
    cudaGetSymbolAddress((void**)&agg_ch, g_agg_ch);
    cudaGetSymbolAddress((void**)&agg_ge, g_agg_ge);
    cudaGetSymbolAddress((void**)&cnt,    g_cnt);
    cudaGetSymbolAddress((void**)&inv,    g_inv);
    cudaGetSymbolAddress((void**)&wt,     g_Wt);

    float* aggs[2] = {agg_ch, agg_ge};
    const int src_nt[4] = {0, 1, 0, 1};   // 0=chemical, 1=gene
    const int dst_nt[4] = {1, 0, 0, 1};

    const int n4 = NNODE * DIM / 4;
    const int edge_blocks = (NE * 64 + 255) / 256;
    dim3 ggrid(2, (NNODE + 127) / 128);   // 2 col blocks x 391 row blocks

    // degrees -> inv
    zero_f4<<<(4 * NNODE / 4 + 255) / 256, 256>>>((float4*)cnt, 4 * NNODE / 4);
    for (int t = 0; t < 4; t++)
        count_deg<<<(NE + 255) / 256, 256>>>(dst[t], NE, cnt + t * NNODE);
    make_inv<<<(4 * NNODE + 255) / 256, 256>>>(cnt, inv, 4 * NNODE);

    // transpose + bf16-split the 6 live weight matrices
    const float* wsrc[6] = {W1[0], W1[1], W1[2], W1[3], W2[1], W2[2]};
    for (int m = 0; m < 6; m++)
        split_w<<<256, 256>>>(wsrc[m], wt + (size_t)m * 131072,
                              wt + (size_t)m * 131072 + 65536);

    // -------- layer 1 (all 4 etypes) --------
    zero_f4<<<(n4 + 255) / 256, 256>>>((float4*)agg_ch, n4);
    zero_f4<<<(n4 + 255) / 256, 256>>>((float4*)agg_ge, n4);
    for (int t = 0; t < 4; t++) {
        gemm_mma<<<ggrid, 256>>>(emb[src_nt[t]],
                                 wt + (size_t)t * 131072,
                                 wt + (size_t)t * 131072 + 65536,
                                 b1[t], wh, NNODE);
        edge_agg<<<edge_blocks, 256>>>(src[t], dst[t], inv + t * NNODE,
                                       wh, aggs[dst_nt[t]], NE);
    }
    leaky_relu_f4<<<(n4 + 255) / 256, 256>>>((float4*)agg_ch, n4);
    leaky_relu_f4<<<(n4 + 255) / 256, 256>>>((float4*)agg_ge, n4);

    // -------- layer 2: only dst==chemical etypes (ge2ch, ch2ch) --------
    zero_f4<<<(n4 + 255) / 256, 256>>>((float4*)d_out, n4);
    gemm_mma<<<ggrid, 256>>>(agg_ge,
                             wt + (size_t)4 * 131072,
                             wt + (size_t)4 * 131072 + 65536,
                             b2[1], wh, NNODE);
    edge_agg<<<edge_blocks, 256>>>(src[1], dst[1], inv + 1 * NNODE,
                                   wh, (float*)d_out, NE);
    gemm_mma<<<ggrid, 256>>>(agg_ch,
                             wt + (size_t)5 * 131072,
                             wt + (size_t)5 * 131072 + 65536,
                             b2[2], wh, NNODE);
    edge_agg<<<edge_blocks, 256>>>(src[2], dst[2], inv + 2 * NNODE,
                                   wh, (float*)d_out, NE);
}

// round 7
// speedup vs baseline: 1.5561x; 1.0402x over previous
#include <cuda_runtime.h>
#include <cuda_bf16.h>
#include <cstdint>

// ---------------------------------------------------------------------------
// Hetero-RGCN, 2 layers, output = chemical nodes.
// GEMM: mma.sync bf16 (HMMA, sm_100-legal) with 3-term bf16 split
//   A*W ~= Ahi*Whi + Alo*Whi + Ahi*Wlo   (fp32 accumulate, rel_err ~5e-6)
// R7: all fp32->bf16 splitting hoisted out of the GEMM into one-shot split
// kernels; GEMM uses cp.async double-buffered smem pipeline (2 CTAs/SM).
// Aggregation: per-edge gather + vector RED with 1/deg scaling (verified).
// ---------------------------------------------------------------------------

#define NNODE 50000
#define DIM   256
#define NE    400000

__device__ __align__(16) float g_Wh[NNODE * DIM];      // per-etype GEMM scratch
__device__ __align__(16) float g_agg_ch[NNODE * DIM];  // layer-1 agg (chemical)
__device__ __align__(16) float g_agg_ge[NNODE * DIM];  // layer-1 agg (gene)
__device__ __align__(16) int   g_cnt[4 * NNODE];
__device__ __align__(16) float g_inv[4 * NNODE];
// 6 weights transposed [N][K], bf16 hi+lo
__device__ __align__(16) __nv_bfloat16 g_Wt[6 * 2 * 65536];
// 4 activation matrices (emb_ch, emb_ge, hid_ch, hid_ge) x (hi,lo), bf16
__device__ __align__(16) __nv_bfloat16 g_Abf[4 * 2 * NNODE * DIM];

// ============================ small utility kernels =========================
__global__ void zero_f4(float4* __restrict__ p, int n4) {
    int i = blockIdx.x * blockDim.x + threadIdx.x;
    if (i < n4) p[i] = make_float4(0.f, 0.f, 0.f, 0.f);
}

__global__ void count_deg(const int* __restrict__ dst, int E, int* __restrict__ cnt) {
    int i = blockIdx.x * blockDim.x + threadIdx.x;
    if (i < E) atomicAdd(&cnt[dst[i]], 1);
}

__global__ void make_inv(const int* __restrict__ cnt, float* __restrict__ inv, int n) {
    int i = blockIdx.x * blockDim.x + threadIdx.x;
    if (i < n) {
        int c = cnt[i];
        inv[i] = 1.0f / (float)(c > 1 ? c : 1);
    }
}

// Transpose + bf16 hi/lo split of one 256x256 weight: out[n][k] = W[k][n]
__global__ void split_w(const float* __restrict__ W,
                        __nv_bfloat16* __restrict__ hi,
                        __nv_bfloat16* __restrict__ lo) {
    int i = blockIdx.x * 256 + threadIdx.x;   // 65536 total
    int n = i >> 8, k = i & 255;
    float w = W[k * 256 + n];
    __nv_bfloat16 h = __float2bfloat16_rn(w);
    hi[i] = h;
    lo[i] = __float2bfloat16_rn(w - __bfloat162float(h));
}

// fp32 activations -> bf16 hi/lo (optionally applying leaky-relu first)
__global__ void split_act(const float* __restrict__ x,
                          __nv_bfloat16* __restrict__ hi,
                          __nv_bfloat16* __restrict__ lo,
                          int n4, int do_lrelu) {
    int i = blockIdx.x * blockDim.x + threadIdx.x;
    if (i >= n4) return;
    float4 v = reinterpret_cast<const float4*>(x)[i];
    if (do_lrelu) {
        v.x = v.x > 0.f ? v.x : 0.01f * v.x;
        v.y = v.y > 0.f ? v.y : 0.01f * v.y;
        v.z = v.z > 0.f ? v.z : 0.01f * v.z;
        v.w = v.w > 0.f ? v.w : 0.01f * v.w;
    }
    __nv_bfloat162 h01, h23, l01, l23;
    h01.x = __float2bfloat16_rn(v.x);
    h01.y = __float2bfloat16_rn(v.y);
    h23.x = __float2bfloat16_rn(v.z);
    h23.y = __float2bfloat16_rn(v.w);
    l01.x = __float2bfloat16_rn(v.x - __bfloat162float(h01.x));
    l01.y = __float2bfloat16_rn(v.y - __bfloat162float(h01.y));
    l23.x = __float2bfloat16_rn(v.z - __bfloat162float(h23.x));
    l23.y = __float2bfloat16_rn(v.w - __bfloat162float(h23.y));
    uint2 hv, lv;
    hv.x = *reinterpret_cast<uint32_t*>(&h01);
    hv.y = *reinterpret_cast<uint32_t*>(&h23);
    lv.x = *reinterpret_cast<uint32_t*>(&l01);
    lv.y = *reinterpret_cast<uint32_t*>(&l23);
    *reinterpret_cast<uint2*>(hi + (size_t)i * 4) = hv;
    *reinterpret_cast<uint2*>(lo + (size_t)i * 4) = lv;
}

// ====================== mma.sync bf16 split GEMM ============================
// C[M x 256] = A[M x 256] @ W + bias.
// A given as pre-split bf16 hi/lo (row-major, k contiguous).
// B given as pre-split, transposed [256 n][256 k] bf16 hi/lo.
// CTA 128(M) x 128(N), BK=32, 256 threads = 8 warps (2 row x 4 col),
// warp tile 64x32, cp.async double-buffered smem.
#define AST 40                 // smem row stride in bf16 (32 data + 8 pad)
#define STG_A_HI 0
#define STG_A_LO 10240
#define STG_B_HI 20480
#define STG_B_LO 30720
#define STG_BYTES 40960
#define SMEM_BYTES (2 * STG_BYTES)   // 81920

__device__ __forceinline__ uint32_t smem_u32(const void* p) {
    uint32_t a;
    asm("{ .reg .u64 t; cvta.to.shared.u64 t, %1; cvt.u32.u64 %0, t; }"
        : "=r"(a) : "l"(p));
    return a;
}

__device__ __forceinline__ void cp16(uint32_t s, const void* g, int sz) {
    asm volatile("cp.async.cg.shared.global [%0], [%1], 16, %2;"
                 :: "r"(s), "l"(g), "r"(sz));
}

__device__ __forceinline__ void mma_bf16(float* c, const uint32_t* a,
                                         const uint32_t* b) {
    asm volatile(
        "mma.sync.aligned.m16n8k16.row.col.f32.bf16.bf16.f32 "
        "{%0,%1,%2,%3}, {%4,%5,%6,%7}, {%8,%9}, {%0,%1,%2,%3};"
        : "+f"(c[0]), "+f"(c[1]), "+f"(c[2]), "+f"(c[3])
        : "r"(a[0]), "r"(a[1]), "r"(a[2]), "r"(a[3]), "r"(b[0]), "r"(b[1]));
}

__global__ __launch_bounds__(256, 2)
void gemm_mma(const __nv_bfloat16* __restrict__ Ahi,
              const __nv_bfloat16* __restrict__ Alo,
              const __nv_bfloat16* __restrict__ Bhi,
              const __nv_bfloat16* __restrict__ Blo,
              const float* __restrict__ bias,
              float* __restrict__ C, int M)
{
    extern __shared__ char smc[];
    const uint32_t smb = smem_u32(smc);

    const int tid = threadIdx.x;
    const int wid = tid >> 5;
    const int lid = tid & 31;
    const int wr = wid & 1;          // warp row (0,1): 64 rows each
    const int wc = wid >> 1;         // warp col (0..3): 32 cols each
    const int g = lid >> 2;          // group 0..7
    const int t = lid & 3;           // thread-in-group
    const int row0 = blockIdx.y * 128;
    const int col0 = blockIdx.x * 128;

    float acc[4][4][4];
#pragma unroll
    for (int i = 0; i < 4; i++)
#pragma unroll
        for (int j = 0; j < 4; j++)
#pragma unroll
            for (int k = 0; k < 4; k++) acc[i][j][k] = 0.f;

    // per-thread loader indices (8 cp.async per stage: 2 iters x 4 matrices)
    const int li0 = tid;                 // 0..255
    // i in 0..511: r = i>>2 (row/n), ch = i&3 (16B chunk within 64B of k)

#define ISSUE_STAGE(stage, k0)                                                 \
    do {                                                                       \
        uint32_t sb = smb + (stage) * STG_BYTES;                               \
        _Pragma("unroll")                                                      \
        for (int it = 0; it < 2; ++it) {                                       \
            int i = it * 256 + li0;                                            \
            int r = i >> 2, ch = i & 3;                                        \
            uint32_t so = (uint32_t)(r * 80 + ch * 16);                        \
            int gr = row0 + r;                                                 \
            int sz = (gr < M) ? 16 : 0;                                        \
            size_t aoff = (size_t)(gr < M ? gr : 0) * 256 + (k0) + ch * 8;     \
            cp16(sb + STG_A_HI + so, Ahi + aoff, sz);                          \
            cp16(sb + STG_A_LO + so, Alo + aoff, sz);                          \
            size_t boff = (size_t)(col0 + r) * 256 + (k0) + ch * 8;            \
            cp16(sb + STG_B_HI + so, Bhi + boff, 16);                          \
            cp16(sb + STG_B_LO + so, Blo + boff, 16);                          \
        }                                                                      \
        asm volatile("cp.async.commit_group;" ::: "memory");                   \
    } while (0)

    ISSUE_STAGE(0, 0);

    for (int kb = 0; kb < 8; ++kb) {
        const int st = kb & 1;
        if (kb < 7) {
            ISSUE_STAGE(st ^ 1, (kb + 1) * 32);
            asm volatile("cp.async.wait_group 1;" ::: "memory");
        } else {
            asm volatile("cp.async.wait_group 0;" ::: "memory");
        }
        __syncthreads();

        const __nv_bfloat16* sAhi =
            reinterpret_cast<const __nv_bfloat16*>(smc + st * STG_BYTES + STG_A_HI);
        const __nv_bfloat16* sAlo =
            reinterpret_cast<const __nv_bfloat16*>(smc + st * STG_BYTES + STG_A_LO);
        const __nv_bfloat16* sBhi =
            reinterpret_cast<const __nv_bfloat16*>(smc + st * STG_BYTES + STG_B_HI);
        const __nv_bfloat16* sBlo =
            reinterpret_cast<const __nv_bfloat16*>(smc + st * STG_BYTES + STG_B_LO);

#pragma unroll
        for (int ks = 0; ks < 2; ++ks) {
            const int kk = ks * 16;
            uint32_t af[4][4], bf[4][2];

            // A-hi fragments
#pragma unroll
            for (int mt = 0; mt < 4; ++mt) {
                const __nv_bfloat16* p = &sAhi[(wr * 64 + mt * 16 + g) * AST + kk + t * 2];
                af[mt][0] = *reinterpret_cast<const uint32_t*>(p);
                af[mt][1] = *reinterpret_cast<const uint32_t*>(p + 8 * AST);
                af[mt][2] = *reinterpret_cast<const uint32_t*>(p + 8);
                af[mt][3] = *reinterpret_cast<const uint32_t*>(p + 8 * AST + 8);
            }
            // B-hi fragments ; term0 = Ahi*Bhi
#pragma unroll
            for (int nt = 0; nt < 4; ++nt) {
                const __nv_bfloat16* p = &sBhi[(wc * 32 + nt * 8 + g) * AST + kk + t * 2];
                bf[nt][0] = *reinterpret_cast<const uint32_t*>(p);
                bf[nt][1] = *reinterpret_cast<const uint32_t*>(p + 8);
            }
#pragma unroll
            for (int mt = 0; mt < 4; ++mt)
#pragma unroll
                for (int nt = 0; nt < 4; ++nt)
                    mma_bf16(acc[mt][nt], af[mt], bf[nt]);

            // B-lo fragments ; term2 = Ahi*Blo
#pragma unroll
            for (int nt = 0; nt < 4; ++nt) {
                const __nv_bfloat16* p = &sBlo[(wc * 32 + nt * 8 + g) * AST + kk + t * 2];
                bf[nt][0] = *reinterpret_cast<const uint32_t*>(p);
                bf[nt][1] = *reinterpret_cast<const uint32_t*>(p + 8);
            }
#pragma unroll
            for (int mt = 0; mt < 4; ++mt)
#pragma unroll
                for (int nt = 0; nt < 4; ++nt)
                    mma_bf16(acc[mt][nt], af[mt], bf[nt]);

            // A-lo fragments, reload B-hi ; term1 = Alo*Bhi
#pragma unroll
            for (int mt = 0; mt < 4; ++mt) {
                const __nv_bfloat16* p = &sAlo[(wr * 64 + mt * 16 + g) * AST + kk + t * 2];
                af[mt][0] = *reinterpret_cast<const uint32_t*>(p);
                af[mt][1] = *reinterpret_cast<const uint32_t*>(p + 8 * AST);
                af[mt][2] = *reinterpret_cast<const uint32_t*>(p + 8);
                af[mt][3] = *reinterpret_cast<const uint32_t*>(p + 8 * AST + 8);
            }
#pragma unroll
            for (int nt = 0; nt < 4; ++nt) {
                const __nv_bfloat16* p = &sBhi[(wc * 32 + nt * 8 + g) * AST + kk + t * 2];
                bf[nt][0] = *reinterpret_cast<const uint32_t*>(p);
                bf[nt][1] = *reinterpret_cast<const uint32_t*>(p + 8);
            }
#pragma unroll
            for (int mt = 0; mt < 4; ++mt)
#pragma unroll
                for (int nt = 0; nt < 4; ++nt)
                    mma_bf16(acc[mt][nt], af[mt], bf[nt]);
        }
        __syncthreads();
    }

    // ---- epilogue: acc + bias -> C ----
#pragma unroll
    for (int nt = 0; nt < 4; ++nt) {
        const int gc = col0 + wc * 32 + nt * 8 + t * 2;
        float2 bb = *reinterpret_cast<const float2*>(bias + gc);
#pragma unroll
        for (int mt = 0; mt < 4; ++mt) {
            int r0 = row0 + wr * 64 + mt * 16 + g;
            if (r0 < M) {
                float2 o;
                o.x = acc[mt][nt][0] + bb.x;
                o.y = acc[mt][nt][1] + bb.y;
                *reinterpret_cast<float2*>(C + (size_t)r0 * 256 + gc) = o;
            }
            if (r0 + 8 < M) {
                float2 o;
                o.x = acc[mt][nt][2] + bb.x;
                o.y = acc[mt][nt][3] + bb.y;
                *reinterpret_cast<float2*>(C + (size_t)(r0 + 8) * 256 + gc) = o;
            }
        }
    }
}

// -------------------------------------------------------- edge aggregation
__global__ void edge_agg(const int* __restrict__ src, const int* __restrict__ dst,
                         const float* __restrict__ inv, const float* __restrict__ Wh,
                         float* __restrict__ agg, int E)
{
    int idx = blockIdx.x * blockDim.x + threadIdx.x;
    int e = idx >> 6;
    if (e >= E) return;
    int q = (idx & 63) << 2;
    int s = __ldg(src + e);
    int d = __ldg(dst + e);
    float w = __ldg(inv + d);
    float4 v = *reinterpret_cast<const float4*>(Wh + (size_t)s * DIM + q);
    float* out = agg + (size_t)d * DIM + q;
    asm volatile("red.global.add.v4.f32 [%0], {%1, %2, %3, %4};"
                 :: "l"(out), "f"(v.x * w), "f"(v.y * w), "f"(v.z * w), "f"(v.w * w)
                 : "memory");
}

// --------------------------------------------------------------------- host
extern "C" void kernel_launch(void* const* d_in, const int* in_sizes, int n_in,
                              void* d_out, int out_size)
{
    (void)n_in; (void)out_size;

    const float* emb[2] = {(const float*)d_in[0], (const float*)d_in[1]};
    const float *W1[4], *b1[4], *W2[4], *b2[4];
    const int *src[4], *dst[4];

    bool dict_order = (in_sizes[6] == NE);
    if (dict_order) {
        for (int t = 0; t < 4; t++) {
            const int base = 2 + 6 * t;
            W1[t]  = (const float*)d_in[base + 0];
            b1[t]  = (const float*)d_in[base + 1];
            W2[t]  = (const float*)d_in[base + 2];
            b2[t]  = (const float*)d_in[base + 3];
            src[t] = (const int*)  d_in[base + 4];
            dst[t] = (const int*)  d_in[base + 5];
        }
    } else {
        for (int t = 0; t < 4; t++) {
            W1[t]  = (const float*)d_in[2  + 2 * t];
            b1[t]  = (const float*)d_in[3  + 2 * t];
            W2[t]  = (const float*)d_in[10 + 2 * t];
            b2[t]  = (const float*)d_in[11 + 2 * t];
            src[t] = (const int*)  d_in[18 + 2 * t];
            dst[t] = (const int*)  d_in[19 + 2 * t];
        }
    }

    float *wh, *agg_ch, *agg_ge, *inv;
    int *cnt;
    __nv_bfloat16 *wt, *abf;
    cudaGetSymbolAddress((void**)&wh,     g_Wh);
    cudaGetSymbolAddress((void**)&agg_ch, g_agg_ch);
    cudaGetSymbolAddress((void**)&agg_ge, g_agg_ge);
    cudaGetSymbolAddress((void**)&cnt,    g_cnt);
    cudaGetSymbolAddress((void**)&inv,    g_inv);
    cudaGetSymbolAddress((void**)&wt,     g_Wt);
    cudaGetSymbolAddress((void**)&abf,    g_Abf);

    cudaFuncSetAttribute(gemm_mma, cudaFuncAttributeMaxDynamicSharedMemorySize,
                         SMEM_BYTES);

    // bf16 activation buffers: 0=emb_ch, 1=emb_ge, 2=hid_ch, 3=hid_ge
    const size_t NB = (size_t)NNODE * DIM;
    __nv_bfloat16* Ah[4];
    __nv_bfloat16* Al[4];
    for (int b = 0; b < 4; b++) {
        Ah[b] = abf + (size_t)(2 * b + 0) * NB;
        Al[b] = abf + (size_t)(2 * b + 1) * NB;
    }

    float* aggs[2] = {agg_ch, agg_ge};
    const int src_nt[4] = {0, 1, 0, 1};   // 0=chemical, 1=gene
    const int dst_nt[4] = {1, 0, 0, 1};

    const int n4 = NNODE * DIM / 4;
    const int edge_blocks = (NE * 64 + 255) / 256;
    dim3 ggrid(2, (NNODE + 127) / 128);

    // degrees -> inv
    zero_f4<<<(4 * NNODE / 4 + 255) / 256, 256>>>((float4*)cnt, 4 * NNODE / 4);
    for (int t = 0; t < 4; t++)
        count_deg<<<(NE + 255) / 256, 256>>>(dst[t], NE, cnt + t * NNODE);
    make_inv<<<(4 * NNODE + 255) / 256, 256>>>(cnt, inv, 4 * NNODE);

    // split the 6 live weights (transpose + hi/lo)
    const float* wsrc[6] = {W1[0], W1[1], W1[2], W1[3], W2[1], W2[2]};
    for (int m = 0; m < 6; m++)
        split_w<<<256, 256>>>(wsrc[m], wt + (size_t)m * 131072,
                              wt + (size_t)m * 131072 + 65536);

    // split input embeddings (no lrelu)
    split_act<<<(n4 + 255) / 256, 256>>>(emb[0], Ah[0], Al[0], n4, 0);
    split_act<<<(n4 + 255) / 256, 256>>>(emb[1], Ah[1], Al[1], n4, 0);

    // -------- layer 1 (all 4 etypes) --------
    zero_f4<<<(n4 + 255) / 256, 256>>>((float4*)agg_ch, n4);
    zero_f4<<<(n4 + 255) / 256, 256>>>((float4*)agg_ge, n4);
    for (int t = 0; t < 4; t++) {
        int b = src_nt[t];
        gemm_mma<<<ggrid, 256, SMEM_BYTES>>>(
            Ah[b], Al[b],
            wt + (size_t)t * 131072, wt + (size_t)t * 131072 + 65536,
            b1[t], wh, NNODE);
        edge_agg<<<edge_blocks, 256>>>(src[t], dst[t], inv + t * NNODE,
                                       wh, aggs[dst_nt[t]], NE);
    }

    // leaky-relu + split hidden states to bf16 hi/lo (buffers 2=ch, 3=ge)
    split_act<<<(n4 + 255) / 256, 256>>>(agg_ch, Ah[2], Al[2], n4, 1);
    split_act<<<(n4 + 255) / 256, 256>>>(agg_ge, Ah[3], Al[3], n4, 1);

    // -------- layer 2: only dst==chemical etypes (ge2ch, ch2ch) --------
    zero_f4<<<(n4 + 255) / 256, 256>>>((float4*)d_out, n4);
    gemm_mma<<<ggrid, 256, SMEM_BYTES>>>(
        Ah[3], Al[3],
        wt + (size_t)4 * 131072, wt + (size_t)4 * 131072 + 65536,
        b2[1], wh, NNODE);
    edge_agg<<<edge_blocks, 256>>>(src[1], dst[1], inv + 1 * NNODE,
                                   wh, (float*)d_out, NE);
    gemm_mma<<<ggrid, 256, SMEM_BYTES>>>(
        Ah[2], Al[2],
        wt + (size_t)5 * 131072, wt + (size_t)5 * 131072 + 65536,
        b2[2], wh, NNODE);
    edge_agg<<<edge_blocks, 256>>>(src[2], dst[2], inv + 2 * NNODE,
                                   wh, (float*)d_out, NE);
}

// round 8
// speedup vs baseline: 2.0267x; 1.3025x over previous
#include <cuda_runtime.h>
#include <cuda_bf16.h>
#include <cstdint>

// ---------------------------------------------------------------------------
// Hetero-RGCN, 2 layers, output = chemical nodes.
// GEMM: mma.sync bf16 (HMMA) 3-term split (Ahi*Whi + Alo*Whi + Ahi*Wlo),
//       cp.async double-buffer + ldmatrix fragment loads (R8).
// Aggregation: CSR (counting-sort by dst) + register accumulation (R8) —
//       one global write per node instead of per-edge L2 RED.
// ---------------------------------------------------------------------------

#define NNODE 50000
#define DIM   256
#define NE    400000

__device__ __align__(16) float g_Wh[NNODE * DIM];      // per-etype GEMM scratch
__device__ __align__(16) float g_agg_ch[NNODE * DIM];
__device__ __align__(16) float g_agg_ge[NNODE * DIM];
__device__ __align__(16) int   g_cnt[4 * NNODE];
__device__ __align__(16) int   g_off[4 * (NNODE + 1)];
__device__ __align__(16) int   g_cur[4 * NNODE];
__device__ __align__(16) int   g_ebuf[4 * NE];
__device__ __align__(16) __nv_bfloat16 g_Wt[6 * 2 * 65536];
__device__ __align__(16) __nv_bfloat16 g_Abf[4 * 2 * NNODE * DIM];

// ============================ small utility kernels =========================
__global__ void zero_i(int* __restrict__ p, int n) {
    int i = blockIdx.x * blockDim.x + threadIdx.x;
    if (i < n) p[i] = 0;
}

__global__ void zero_f4(float4* __restrict__ p, int n4) {
    int i = blockIdx.x * blockDim.x + threadIdx.x;
    if (i < n4) p[i] = make_float4(0.f, 0.f, 0.f, 0.f);
}

__global__ void count_deg(const int* __restrict__ dst, int E, int* __restrict__ cnt) {
    int i = blockIdx.x * blockDim.x + threadIdx.x;
    if (i < E) atomicAdd(&cnt[dst[i]], 1);
}

// one block per etype: exclusive scan of 50000 counts -> offsets
__global__ __launch_bounds__(1024)
void scan_cnt(const int* __restrict__ cnt, int* __restrict__ off) {
    const int et = blockIdx.x;
    const int* c = cnt + et * NNODE;
    int* o = off + et * (NNODE + 1);
    __shared__ int buf[1024];
    __shared__ int s_carry;
    if (threadIdx.x == 0) { s_carry = 0; o[0] = 0; }
    __syncthreads();
    for (int base = 0; base < NNODE; base += 1024) {
        int i = base + threadIdx.x;
        int v = (i < NNODE) ? c[i] : 0;
        buf[threadIdx.x] = v;
        __syncthreads();
#pragma unroll
        for (int d = 1; d < 1024; d <<= 1) {
            int add = (threadIdx.x >= d) ? buf[threadIdx.x - d] : 0;
            __syncthreads();
            buf[threadIdx.x] += add;
            __syncthreads();
        }
        if (i < NNODE) o[i + 1] = buf[threadIdx.x] + s_carry;
        __syncthreads();
        if (threadIdx.x == 0) s_carry += buf[1023];
        __syncthreads();
    }
}

__global__ void scatter_edges(const int* __restrict__ src, const int* __restrict__ dst,
                              const int* __restrict__ off, int* __restrict__ cur,
                              int* __restrict__ ebuf, int E) {
    int e = blockIdx.x * blockDim.x + threadIdx.x;
    if (e >= E) return;
    int d = dst[e];
    int p = atomicAdd(&cur[d], 1);
    ebuf[off[d] + p] = src[e];
}

// Transpose + bf16 hi/lo split of one 256x256 weight: out[n][k] = W[k][n]
__global__ void split_w(const float* __restrict__ W,
                        __nv_bfloat16* __restrict__ hi,
                        __nv_bfloat16* __restrict__ lo) {
    int i = blockIdx.x * 256 + threadIdx.x;
    int n = i >> 8, k = i & 255;
    float w = W[k * 256 + n];
    __nv_bfloat16 h = __float2bfloat16_rn(w);
    hi[i] = h;
    lo[i] = __float2bfloat16_rn(w - __bfloat162float(h));
}

// fp32 activations -> bf16 hi/lo (optional leaky-relu first)
__global__ void split_act(const float* __restrict__ x,
                          __nv_bfloat16* __restrict__ hi,
                          __nv_bfloat16* __restrict__ lo,
                          int n4, int do_lrelu) {
    int i = blockIdx.x * blockDim.x + threadIdx.x;
    if (i >= n4) return;
    float4 v = reinterpret_cast<const float4*>(x)[i];
    if (do_lrelu) {
        v.x = v.x > 0.f ? v.x : 0.01f * v.x;
        v.y = v.y > 0.f ? v.y : 0.01f * v.y;
        v.z = v.z > 0.f ? v.z : 0.01f * v.z;
        v.w = v.w > 0.f ? v.w : 0.01f * v.w;
    }
    __nv_bfloat162 h01, h23, l01, l23;
    h01.x = __float2bfloat16_rn(v.x);
    h01.y = __float2bfloat16_rn(v.y);
    h23.x = __float2bfloat16_rn(v.z);
    h23.y = __float2bfloat16_rn(v.w);
    l01.x = __float2bfloat16_rn(v.x - __bfloat162float(h01.x));
    l01.y = __float2bfloat16_rn(v.y - __bfloat162float(h01.y));
    l23.x = __float2bfloat16_rn(v.z - __bfloat162float(h23.x));
    l23.y = __float2bfloat16_rn(v.w - __bfloat162float(h23.y));
    uint2 hv, lv;
    hv.x = *reinterpret_cast<uint32_t*>(&h01);
    hv.y = *reinterpret_cast<uint32_t*>(&h23);
    lv.x = *reinterpret_cast<uint32_t*>(&l01);
    lv.y = *reinterpret_cast<uint32_t*>(&l23);
    *reinterpret_cast<uint2*>(hi + (size_t)i * 4) = hv;
    *reinterpret_cast<uint2*>(lo + (size_t)i * 4) = lv;
}

// ====================== mma.sync bf16 split GEMM ============================
#define AST 40                 // smem row stride in bf16 (32 data + 8 pad)
#define STG_A_HI 0
#define STG_A_LO 10240
#define STG_B_HI 20480
#define STG_B_LO 30720
#define STG_BYTES 40960
#define SMEM_BYTES (2 * STG_BYTES)   // 81920

__device__ __forceinline__ uint32_t smem_u32(const void* p) {
    uint32_t a;
    asm("{ .reg .u64 t; cvta.to.shared.u64 t, %1; cvt.u32.u64 %0, t; }"
        : "=r"(a) : "l"(p));
    return a;
}

__device__ __forceinline__ void cp16(uint32_t s, const void* g, int sz) {
    asm volatile("cp.async.cg.shared.global [%0], [%1], 16, %2;"
                 :: "r"(s), "l"(g), "r"(sz));
}

__device__ __forceinline__ void ldm_x4(uint32_t* r, uint32_t addr) {
    asm volatile("ldmatrix.sync.aligned.m8n8.x4.shared.b16 {%0,%1,%2,%3}, [%4];"
                 : "=r"(r[0]), "=r"(r[1]), "=r"(r[2]), "=r"(r[3]) : "r"(addr));
}

__device__ __forceinline__ void mma_bf16(float* c, const uint32_t* a,
                                         const uint32_t* b) {
    asm volatile(
        "mma.sync.aligned.m16n8k16.row.col.f32.bf16.bf16.f32 "
        "{%0,%1,%2,%3}, {%4,%5,%6,%7}, {%8,%9}, {%0,%1,%2,%3};"
        : "+f"(c[0]), "+f"(c[1]), "+f"(c[2]), "+f"(c[3])
        : "r"(a[0]), "r"(a[1]), "r"(a[2]), "r"(a[3]), "r"(b[0]), "r"(b[1]));
}

__global__ __launch_bounds__(256, 2)
void gemm_mma(const __nv_bfloat16* __restrict__ Ahi,
              const __nv_bfloat16* __restrict__ Alo,
              const __nv_bfloat16* __restrict__ Bhi,
              const __nv_bfloat16* __restrict__ Blo,
              const float* __restrict__ bias,
              float* __restrict__ C, int M)
{
    extern __shared__ char smc[];
    const uint32_t smb = smem_u32(smc);

    const int tid = threadIdx.x;
    const int wid = tid >> 5;
    const int lid = tid & 31;
    const int wr = wid & 1;
    const int wc = wid >> 1;
    const int g = lid >> 2;
    const int t = lid & 3;
    const int row0 = blockIdx.y * 128;
    const int col0 = blockIdx.x * 128;

    // ldmatrix per-lane address components (element units, bf16)
    const int a_row_l = wr * 64 + (lid & 7) + ((lid >> 3) & 1) * 8;  // + mt*16
    const int a_col_l = ((lid >> 4) & 1) * 8;                        // + kk
    const int b_row_l = wc * 32 + (lid & 7) + ((lid >> 4) & 1) * 8;  // + np*16
    const int b_col_l = ((lid >> 3) & 1) * 8;                        // + kk

    float acc[4][4][4];
#pragma unroll
    for (int i = 0; i < 4; i++)
#pragma unroll
        for (int j = 0; j < 4; j++)
#pragma unroll
            for (int k = 0; k < 4; k++) acc[i][j][k] = 0.f;

#define ISSUE_STAGE(stage, k0)                                                 \
    do {                                                                       \
        uint32_t sb = smb + (stage) * STG_BYTES;                               \
        _Pragma("unroll")                                                      \
        for (int it = 0; it < 2; ++it) {                                       \
            int i = it * 256 + tid;                                            \
            int r = i >> 2, ch = i & 3;                                        \
            uint32_t so = (uint32_t)(r * 80 + ch * 16);                        \
            int gr = row0 + r;                                                 \
            int sz = (gr < M) ? 16 : 0;                                        \
            size_t aoff = (size_t)(gr < M ? gr : 0) * 256 + (k0) + ch * 8;     \
            cp16(sb + STG_A_HI + so, Ahi + aoff, sz);                          \
            cp16(sb + STG_A_LO + so, Alo + aoff, sz);                          \
            size_t boff = (size_t)(col0 + r) * 256 + (k0) + ch * 8;            \
            cp16(sb + STG_B_HI + so, Bhi + boff, 16);                          \
            cp16(sb + STG_B_LO + so, Blo + boff, 16);                          \
        }                                                                      \
        asm volatile("cp.async.commit_group;" ::: "memory");                   \
    } while (0)

    ISSUE_STAGE(0, 0);

    for (int kb = 0; kb < 8; ++kb) {
        const int st = kb & 1;
        if (kb < 7) {
            ISSUE_STAGE(st ^ 1, (kb + 1) * 32);
            asm volatile("cp.async.wait_group 1;" ::: "memory");
        } else {
            asm volatile("cp.async.wait_group 0;" ::: "memory");
        }
        __syncthreads();

        const uint32_t stg = smb + st * STG_BYTES;

#pragma unroll
        for (int ks = 0; ks < 2; ++ks) {
            const int kk = ks * 16;
            uint32_t af[4][4], bh[2][4], bl[2][4];

            // B-hi / B-lo fragments: 2 ldmatrix.x4 each (two n8 tiles per x4)
#pragma unroll
            for (int np = 0; np < 2; ++np) {
                uint32_t boff = (uint32_t)((b_row_l + np * 16) * AST + kk + b_col_l) * 2;
                ldm_x4(bh[np], stg + STG_B_HI + boff);
                ldm_x4(bl[np], stg + STG_B_LO + boff);
            }
            // A-hi fragments: 4 ldmatrix.x4
#pragma unroll
            for (int mt = 0; mt < 4; ++mt) {
                uint32_t aoff = (uint32_t)((a_row_l + mt * 16) * AST + kk + a_col_l) * 2;
                ldm_x4(af[mt], stg + STG_A_HI + aoff);
            }
            // term0 = Ahi*Bhi ; term2 = Ahi*Blo
#pragma unroll
            for (int mt = 0; mt < 4; ++mt)
#pragma unroll
                for (int nt = 0; nt < 4; ++nt)
                    mma_bf16(acc[mt][nt], af[mt], &bh[nt >> 1][(nt & 1) * 2]);
#pragma unroll
            for (int mt = 0; mt < 4; ++mt)
#pragma unroll
                for (int nt = 0; nt < 4; ++nt)
                    mma_bf16(acc[mt][nt], af[mt], &bl[nt >> 1][(nt & 1) * 2]);
            // A-lo fragments overwrite A-hi ; term1 = Alo*Bhi
#pragma unroll
            for (int mt = 0; mt < 4; ++mt) {
                uint32_t aoff = (uint32_t)((a_row_l + mt * 16) * AST + kk + a_col_l) * 2;
                ldm_x4(af[mt], stg + STG_A_LO + aoff);
            }
#pragma unroll
            for (int mt = 0; mt < 4; ++mt)
#pragma unroll
                for (int nt = 0; nt < 4; ++nt)
                    mma_bf16(acc[mt][nt], af[mt], &bh[nt >> 1][(nt & 1) * 2]);
        }
        __syncthreads();
    }

    // ---- epilogue: acc + bias -> C ----
#pragma unroll
    for (int nt = 0; nt < 4; ++nt) {
        const int gc = col0 + wc * 32 + nt * 8 + t * 2;
        float2 bb = *reinterpret_cast<const float2*>(bias + gc);
#pragma unroll
        for (int mt = 0; mt < 4; ++mt) {
            int r0 = row0 + wr * 64 + mt * 16 + g;
            if (r0 < M) {
                float2 o;
                o.x = acc[mt][nt][0] + bb.x;
                o.y = acc[mt][nt][1] + bb.y;
                *reinterpret_cast<float2*>(C + (size_t)r0 * 256 + gc) = o;
            }
            if (r0 + 8 < M) {
                float2 o;
                o.x = acc[mt][nt][2] + bb.x;
                o.y = acc[mt][nt][3] + bb.y;
                *reinterpret_cast<float2*>(C + (size_t)(r0 + 8) * 256 + gc) = o;
            }
        }
    }
}

// ------------------------------------------------- CSR mean aggregation
// 64 threads per dst node, each owns one float4 column chunk; register
// accumulate over the node's edge list, single global write per node.
__global__ void csr_agg(const int* __restrict__ off, const int* __restrict__ ebuf,
                        const float* __restrict__ Wh, float* __restrict__ agg)
{
    int idx = blockIdx.x * blockDim.x + threadIdx.x;
    int node = idx >> 6;
    if (node >= NNODE) return;
    int q = (idx & 63) << 2;
    int e0 = __ldg(off + node), e1 = __ldg(off + node + 1);
    if (e0 == e1) return;
    float4 s = make_float4(0.f, 0.f, 0.f, 0.f);
    for (int e = e0; e < e1; ++e) {
        int sidx = __ldg(ebuf + e);
        float4 v = *reinterpret_cast<const float4*>(Wh + (size_t)sidx * DIM + q);
        s.x += v.x; s.y += v.y; s.z += v.z; s.w += v.w;
    }
    float w = 1.0f / (float)(e1 - e0);
    float4* out = reinterpret_cast<float4*>(agg + (size_t)node * DIM + q);
    float4 a = *out;
    a.x += s.x * w; a.y += s.y * w; a.z += s.z * w; a.w += s.w * w;
    *out = a;
}

// --------------------------------------------------------------------- host
extern "C" void kernel_launch(void* const* d_in, const int* in_sizes, int n_in,
                              void* d_out, int out_size)
{
    (void)n_in; (void)out_size;

    const float* emb[2] = {(const float*)d_in[0], (const float*)d_in[1]};
    const float *W1[4], *b1[4], *W2[4], *b2[4];
    const int *src[4], *dst[4];

    bool dict_order = (in_sizes[6] == NE);
    if (dict_order) {
        for (int t = 0; t < 4; t++) {
            const int base = 2 + 6 * t;
            W1[t]  = (const float*)d_in[base + 0];
            b1[t]  = (const float*)d_in[base + 1];
            W2[t]  = (const float*)d_in[base + 2];
            b2[t]  = (const float*)d_in[base + 3];
            src[t] = (const int*)  d_in[base + 4];
            dst[t] = (const int*)  d_in[base + 5];
        }
    } else {
        for (int t = 0; t < 4; t++) {
            W1[t]  = (const float*)d_in[2  + 2 * t];
            b1[t]  = (const float*)d_in[3  + 2 * t];
            W2[t]  = (const float*)d_in[10 + 2 * t];
            b2[t]  = (const float*)d_in[11 + 2 * t];
            src[t] = (const int*)  d_in[18 + 2 * t];
            dst[t] = (const int*)  d_in[19 + 2 * t];
        }
    }

    float *wh, *agg_ch, *agg_ge;
    int *cnt, *off, *cur, *ebuf;
    __nv_bfloat16 *wt, *abf;
    cudaGetSymbolAddress((void**)&wh,     g_Wh);
    cudaGetSymbolAddress((void**)&agg_ch, g_agg_ch);
    cudaGetSymbolAddress((void**)&agg_ge, g_agg_ge);
    cudaGetSymbolAddress((void**)&cnt,    g_cnt);
    cudaGetSymbolAddress((void**)&off,    g_off);
    cudaGetSymbolAddress((void**)&cur,    g_cur);
    cudaGetSymbolAddress((void**)&ebuf,   g_ebuf);
    cudaGetSymbolAddress((void**)&wt,     g_Wt);
    cudaGetSymbolAddress((void**)&abf,    g_Abf);

    cudaFuncSetAttribute(gemm_mma, cudaFuncAttributeMaxDynamicSharedMemorySize,
                         SMEM_BYTES);

    const size_t NB = (size_t)NNODE * DIM;
    __nv_bfloat16* Ah[4];
    __nv_bfloat16* Al[4];
    for (int b = 0; b < 4; b++) {
        Ah[b] = abf + (size_t)(2 * b + 0) * NB;
        Al[b] = abf + (size_t)(2 * b + 1) * NB;
    }

    float* aggs[2] = {agg_ch, agg_ge};
    const int src_nt[4] = {0, 1, 0, 1};   // 0=chemical, 1=gene
    const int dst_nt[4] = {1, 0, 0, 1};

    const int n4 = NNODE * DIM / 4;
    const int agg_blocks = (NNODE * 64 + 255) / 256;
    dim3 ggrid(2, (NNODE + 127) / 128);

    // ---- build per-etype CSR (counting sort by dst) ----
    zero_i<<<(4 * NNODE + 255) / 256, 256>>>(cnt, 4 * NNODE);
    zero_i<<<(4 * NNODE + 255) / 256, 256>>>(cur, 4 * NNODE);
    for (int t = 0; t < 4; t++)
        count_deg<<<(NE + 255) / 256, 256>>>(dst[t], NE, cnt + t * NNODE);
    scan_cnt<<<4, 1024>>>(cnt, off);
    for (int t = 0; t < 4; t++)
        scatter_edges<<<(NE + 255) / 256, 256>>>(src[t], dst[t],
                                                 off + t * (NNODE + 1),
                                                 cur + t * NNODE,
                                                 ebuf + t * NE, NE);

    // ---- weight + activation splits ----
    const float* wsrc[6] = {W1[0], W1[1], W1[2], W1[3], W2[1], W2[2]};
    for (int m = 0; m < 6; m++)
        split_w<<<256, 256>>>(wsrc[m], wt + (size_t)m * 131072,
                              wt + (size_t)m * 131072 + 65536);
    split_act<<<(n4 + 255) / 256, 256>>>(emb[0], Ah[0], Al[0], n4, 0);
    split_act<<<(n4 + 255) / 256, 256>>>(emb[1], Ah[1], Al[1], n4, 0);

    // -------- layer 1 (all 4 etypes) --------
    zero_f4<<<(n4 + 255) / 256, 256>>>((float4*)agg_ch, n4);
    zero_f4<<<(n4 + 255) / 256, 256>>>((float4*)agg_ge, n4);
    for (int t = 0; t < 4; t++) {
        int b = src_nt[t];
        gemm_mma<<<ggrid, 256, SMEM_BYTES>>>(
            Ah[b], Al[b],
            wt + (size_t)t * 131072, wt + (size_t)t * 131072 + 65536,
            b1[t], wh, NNODE);
        csr_agg<<<agg_blocks, 256>>>(off + t * (NNODE + 1), ebuf + t * NE,
                                     wh, aggs[dst_nt[t]]);
    }

    // leaky-relu + split hidden states (buffers 2=ch, 3=ge)
    split_act<<<(n4 + 255) / 256, 256>>>(agg_ch, Ah[2], Al[2], n4, 1);
    split_act<<<(n4 + 255) / 256, 256>>>(agg_ge, Ah[3], Al[3], n4, 1);

    // -------- layer 2: only dst==chemical etypes (ge2ch, ch2ch) --------
    zero_f4<<<(n4 + 255) / 256, 256>>>((float4*)d_out, n4);
    gemm_mma<<<ggrid, 256, SMEM_BYTES>>>(
        Ah[3], Al[3],
        wt + (size_t)4 * 131072, wt + (size_t)4 * 131072 + 65536,
        b2[1], wh, NNODE);
    csr_agg<<<agg_blocks, 256>>>(off + 1 * (NNODE + 1), ebuf + 1 * NE,
                                 wh, (float*)d_out);
    gemm_mma<<<ggrid, 256, SMEM_BYTES>>>(
        Ah[2], Al[2],
        wt + (size_t)5 * 131072, wt + (size_t)5 * 131072 + 65536,
        b2[2], wh, NNODE);
    csr_agg<<<agg_blocks, 256>>>(off + 2 * (NNODE + 1), ebuf + 2 * NE,
                                 wh, (float*)d_out);
}